// round 6
// baseline (speedup 1.0000x reference)
#include <cuda_runtime.h>
#include <cuda_fp16.h>
#include <cstdint>

#define NN   12288
#define KK   32
#define DD   128

typedef unsigned long long ull;

// Scratch: G = raw_features @ W_lin^T, stored as fp16 (N x 128, 3.15 MB)
__device__ __align__(16) __half g_Gh[NN * DD];

// ---------------------------------------------------------------------------
// packed f32x2 helpers (sm_103a FFMA2 via PTX fma.rn.f32x2)
// ---------------------------------------------------------------------------
__device__ __forceinline__ ull pack_dup(float x) {
    ull r;
    asm("mov.b64 %0, {%1, %1};" : "=l"(r) : "f"(x));
    return r;
}
__device__ __forceinline__ void fma2(ull& d, ull a, ull b) {
    asm("fma.rn.f32x2 %0, %1, %2, %0;" : "+l"(d) : "l"(a), "l"(b));
}
__device__ __forceinline__ void unpack2(float& lo, float& hi, ull v) {
    asm("mov.b64 {%0, %1}, %2;" : "=f"(lo), "=f"(hi) : "l"(v));
}

// ---------------------------------------------------------------------------
// Kernel 1: G[m][n] = sum_k F[m][k] * W[n][k], output fp16.
// Grid (192, 2): 64x64 tiles, 128 threads, 3 CTAs/SM.
// Microtile 8 rows x 4 cols, accumulators paired over rows (FFMA2).
// ---------------------------------------------------------------------------
__global__ void __launch_bounds__(128, 3)
gemm_G_kernel(const float* __restrict__ F, const float* __restrict__ W)
{
    extern __shared__ float sm[];
    float* Fst = sm;                 // 128 * 66  (Fst[k*66 + m])
    float* Wt  = sm + 128 * 66;      // 128 * 66  (Wt [k*66 + n])

    const int tid = threadIdx.x;
    const int bm  = blockIdx.x;
    const int bn  = blockIdx.y;

    const float* Fblk = F + (size_t)bm * 64 * DD;
    const float* Wblk = W + (size_t)bn * 64 * DD;

    #pragma unroll 8
    for (int idx = tid; idx < 64 * 128; idx += 128) {
        int r = idx >> 7, k = idx & 127;
        Fst[k * 66 + r] = Fblk[idx];
        Wt [k * 66 + r] = Wblk[idx];
    }
    __syncthreads();

    const int tx = tid & 15;   // cols 4*tx .. 4*tx+3
    const int ty = tid >> 4;   // rows 8*ty .. 8*ty+7

    ull acc[4][4];
    #pragma unroll
    for (int p = 0; p < 4; p++)
        #pragma unroll
        for (int c = 0; c < 4; c++)
            acc[p][c] = 0ULL;

    #pragma unroll 4
    for (int kk = 0; kk < 128; kk++) {
        const float* fr = &Fst[kk * 66 + 8 * ty];
        ull a2[4];
        #pragma unroll
        for (int p = 0; p < 4; p++)
            a2[p] = *reinterpret_cast<const ull*>(&fr[2 * p]);

        float2 b01 = *reinterpret_cast<const float2*>(&Wt[kk * 66 + 4 * tx]);
        float2 b23 = *reinterpret_cast<const float2*>(&Wt[kk * 66 + 4 * tx + 2]);
        ull bd[4];
        bd[0] = pack_dup(b01.x); bd[1] = pack_dup(b01.y);
        bd[2] = pack_dup(b23.x); bd[3] = pack_dup(b23.y);

        #pragma unroll
        for (int p = 0; p < 4; p++)
            #pragma unroll
            for (int c = 0; c < 4; c++)
                fma2(acc[p][c], a2[p], bd[c]);
    }

    // Epilogue: unpack to v[row][col], convert to half, 8B stores.
    float v[8][4];
    #pragma unroll
    for (int p = 0; p < 4; p++)
        #pragma unroll
        for (int c = 0; c < 4; c++) {
            float lo, hi;
            unpack2(lo, hi, acc[p][c]);
            v[2 * p][c]     = lo;
            v[2 * p + 1][c] = hi;
        }

    const int gm0 = bm * 64 + 8 * ty;
    const int gn0 = bn * 64 + 4 * tx;
    #pragma unroll
    for (int r = 0; r < 8; r++) {
        __half2 h01 = __floats2half2_rn(v[r][0], v[r][1]);
        __half2 h23 = __floats2half2_rn(v[r][2], v[r][3]);
        uint2 st;
        st.x = *reinterpret_cast<unsigned*>(&h01);
        st.y = *reinterpret_cast<unsigned*>(&h23);
        *reinterpret_cast<uint2*>(&g_Gh[(size_t)(gm0 + r) * DD + gn0]) = st;
    }
}

// ---------------------------------------------------------------------------
// Kernel 2: out[b][d] = relu( sum_k w[b][k] * G[nb[b][k]][d] + bias[d] )
// 8 nodes / 256-thread block; warp per node, lane owns 4 cols (half4 = uint2).
// k in chunks of 8 (MLP=8, 16 regs of payload). fp32 accumulate.
// ---------------------------------------------------------------------------
__global__ void __launch_bounds__(256)
gather_kernel(const int* __restrict__ nodes,
              const int* __restrict__ neighbors,
              const float* __restrict__ rew,
              const float* __restrict__ b_lin,
              float* __restrict__ out)
{
    __shared__ int   nb_s[8][KK];
    __shared__ float w_s [8][KK];

    const int tid = threadIdx.x;
    const int b0  = blockIdx.x * 8;

    {   // 256 threads == 8 nodes x 32 k exactly
        const int ln = tid >> 5;
        const int k  = tid & 31;
        const int b  = b0 + ln;
        const int node = nodes[b];
        const int nb   = neighbors[b * KK + k];
        float w = 0.0f;
        if (nb != node)
            w = __ldg(&rew[(size_t)node * NN + nb]);
        nb_s[ln][k] = nb;
        w_s [ln][k] = w;
    }
    __syncthreads();

    const int ln   = tid >> 5;
    const int lane = tid & 31;
    const int d4   = lane * 4;
    const int b    = b0 + ln;

    float4 acc = make_float4(0.f, 0.f, 0.f, 0.f);

    #pragma unroll
    for (int kb = 0; kb < KK; kb += 8) {
        uint2 g[8];
        float wv[8];
        #pragma unroll
        for (int u = 0; u < 8; u++) {
            const int nb = nb_s[ln][kb + u];
            wv[u] = w_s[ln][kb + u];
            g[u]  = __ldg(reinterpret_cast<const uint2*>(
                              &g_Gh[(size_t)nb * DD + d4]));
        }
        #pragma unroll
        for (int u = 0; u < 8; u++) {
            float2 lo = __half22float2(*reinterpret_cast<__half2*>(&g[u].x));
            float2 hi = __half22float2(*reinterpret_cast<__half2*>(&g[u].y));
            acc.x = fmaf(wv[u], lo.x, acc.x);
            acc.y = fmaf(wv[u], lo.y, acc.y);
            acc.z = fmaf(wv[u], hi.x, acc.z);
            acc.w = fmaf(wv[u], hi.y, acc.w);
        }
    }

    const float4 bias = __ldg(reinterpret_cast<const float4*>(&b_lin[d4]));
    float4 o;
    o.x = fmaxf(acc.x + bias.x, 0.f);
    o.y = fmaxf(acc.y + bias.y, 0.f);
    o.z = fmaxf(acc.z + bias.z, 0.f);
    o.w = fmaxf(acc.w + bias.w, 0.f);
    *reinterpret_cast<float4*>(&out[(size_t)b * DD + d4]) = o;
}

// ---------------------------------------------------------------------------
// Launch. Inputs: nodes(i32 N), neighbors(i32 N*K), raw_features(f32 N*128),
//                 reweighted(f32 N*N), W_lin(f32 128*128), b_lin(f32 128)
// ---------------------------------------------------------------------------
extern "C" void kernel_launch(void* const* d_in, const int* in_sizes, int n_in,
                              void* d_out, int out_size)
{
    const int*   nodes      = (const int*)  d_in[0];
    const int*   neighbors  = (const int*)  d_in[1];
    const float* raw_feats  = (const float*)d_in[2];
    const float* reweighted = (const float*)d_in[3];
    const float* W_lin      = (const float*)d_in[4];
    const float* b_lin      = (const float*)d_in[5];
    float*       out        = (float*)d_out;

    const int smem = 2 * 128 * 66 * (int)sizeof(float);  // 67584 B
    static bool attr_set = false;
    if (!attr_set) {
        cudaFuncSetAttribute(gemm_G_kernel,
                             cudaFuncAttributeMaxDynamicSharedMemorySize, smem);
        attr_set = true;
    }

    dim3 ggrid(NN / 64, DD / 64);
    gemm_G_kernel<<<ggrid, 128, smem>>>(raw_feats, W_lin);
    gather_kernel<<<NN / 8, 256>>>(nodes, neighbors, reweighted, b_lin, out);
}